// round 5
// baseline (speedup 1.0000x reference)
#include <cuda_runtime.h>
#include <cuda_bf16.h>
#include <math_constants.h>
#include <cstdint>

#define BATCH 2
#define CH    64
#define HH    80
#define WWW   80
#define NPIX  6400   // 80*80
#define NHALF (NPIX / 2)    // 3200 keys per warpgroup
#define NT2   (NHALF / 64)  // 50 key tiles per warpgroup
#define PIT   72            // padded smem row pitch in bf16 elems (144B)

// dynamic smem layout (bytes)
#define SQ_BYTES   (64 * PIT * 2)            // 9216
#define TILE_BYTES (64 * PIT * 2)            // 9216 per K or V tile
#define WG_BYTES   (4 * TILE_BYTES)          // 2 bufs x (K,V) = 36864
#define SMEM_ATTN  (SQ_BYTES + 2 * WG_BYTES) // 82944

// ---------------- device scratch (static, allocation-free) ----------------
__device__ __align__(16) __nv_bfloat16 g_Q[BATCH * NPIX * CH]; // [b][n][c], *0.125*log2e
__device__ __align__(16) __nv_bfloat16 g_K[BATCH * NPIX * CH]; // [b][n][c]
__device__ __align__(16) __nv_bfloat16 g_V[BATCH * NPIX * CH]; // [b][n][c]
__device__ float g_L[BATCH * CH * NPIX];                       // low, [b][c][n]

// ---------------- PTX helpers ----------------
#define LDSM_X4(R0,R1,R2,R3,ADDR) \
  asm volatile("ldmatrix.sync.aligned.m8n8.x4.shared.b16 {%0,%1,%2,%3},[%4];" \
    : "=r"(R0),"=r"(R1),"=r"(R2),"=r"(R3) : "r"(ADDR))
#define LDSM_X4T(R0,R1,R2,R3,ADDR) \
  asm volatile("ldmatrix.sync.aligned.m8n8.x4.trans.shared.b16 {%0,%1,%2,%3},[%4];" \
    : "=r"(R0),"=r"(R1),"=r"(R2),"=r"(R3) : "r"(ADDR))
#define LDSM_X2(R0,R1,ADDR) \
  asm volatile("ldmatrix.sync.aligned.m8n8.x2.shared.b16 {%0,%1},[%2];" \
    : "=r"(R0),"=r"(R1) : "r"(ADDR))
#define MMA16816(D,A0,A1,A2,A3,B0,B1) \
  asm volatile("mma.sync.aligned.m16n8k16.row.col.f32.bf16.bf16.f32 " \
    "{%0,%1,%2,%3},{%4,%5,%6,%7},{%8,%9},{%0,%1,%2,%3};" \
    : "+f"(D[0]),"+f"(D[1]),"+f"(D[2]),"+f"(D[3]) \
    : "r"(A0),"r"(A1),"r"(A2),"r"(A3),"r"(B0),"r"(B1))
#define CP_ASYNC16(SMEM_U32, GPTR) \
  asm volatile("cp.async.cg.shared.global [%0], [%1], 16;" :: "r"(SMEM_U32), "l"(GPTR))
#define CP_COMMIT()  asm volatile("cp.async.commit_group;" ::: "memory")
#define CP_WAIT1()   asm volatile("cp.async.wait_group 1;" ::: "memory")
#define CP_WAIT0()   asm volatile("cp.async.wait_group 0;" ::: "memory")

__device__ __forceinline__ uint32_t pack_bf16(float lo, float hi) {
    uint32_t r;
    asm("cvt.rn.bf16x2.f32 %0, %1, %2;" : "=r"(r) : "f"(hi), "f"(lo));
    return r;
}

// ---------------- kernel 1: fused maxpool3 + maxpool5 -> low ----------------
__global__ void pool_kernel(const float* __restrict__ x) {
    int idx = blockIdx.x * 256 + threadIdx.x;
    if (idx >= BATCH * CH * NPIX) return;
    int w  = idx % WWW;
    int h  = (idx / WWW) % HH;
    int bc = idx / NPIX;
    const float* xp = x + (size_t)bc * NPIX;
    float m3 = -CUDART_INF_F, m5 = -CUDART_INF_F;
    #pragma unroll
    for (int dy = -2; dy <= 2; dy++) {
        int hh = h + dy;
        if (hh < 0 || hh >= HH) continue;
        const float* row = xp + hh * WWW;
        #pragma unroll
        for (int dx = -2; dx <= 2; dx++) {
            int ww = w + dx;
            if (ww < 0 || ww >= WWW) continue;
            float v = row[ww];
            m5 = fmaxf(m5, v);
            if (dy >= -1 && dy <= 1 && dx >= -1 && dx <= 1) m3 = fmaxf(m3, v);
        }
    }
    g_L[idx] = 0.5f * (m3 + m5);
}

// ---------------- kernel 2: Q,K,V projections (bf16 out) ----------------
__global__ __launch_bounds__(256) void qkv_kernel(
    const float* __restrict__ x,
    const float* __restrict__ q1w, const float* __restrict__ q1g, const float* __restrict__ q1b,
    const float* __restrict__ q2w, const float* __restrict__ q2g, const float* __restrict__ q2b,
    const float* __restrict__ q3w, const float* __restrict__ q3g, const float* __restrict__ q3b,
    const float* __restrict__ khw, const float* __restrict__ khb,
    const float* __restrict__ klw, const float* __restrict__ klb,
    const float* __restrict__ kfw, const float* __restrict__ kfb,
    const float* __restrict__ vg,  const float* __restrict__ vbn,
    const float* __restrict__ vw,  const float* __restrict__ vb)
{
    __shared__ float xs[CH * 64];
    __shared__ float ls[CH * 64];
    __shared__ float ts[64 * CH];

    int b  = blockIdx.y;
    int n0 = blockIdx.x * 64;
    int tid = threadIdx.x;
    int c  = tid & 63;
    int pq = tid >> 6;

    for (int i = tid; i < CH * 64; i += 256) {
        int cc = i >> 6, pp = i & 63;
        size_t gi = (size_t)(b * CH + cc) * NPIX + n0 + pp;
        xs[i] = x[gi];
        ls[i] = g_L[gi];
    }
    __syncthreads();

    const float inv = rsqrtf(1.0f + 1e-5f);   // BN eval: running_var=1
    const float QSCALE = 0.125f * 1.4426950408889634f;  // 1/sqrt(64) * log2(e)

    // ---- Q: grouped 1x1 conv -> BN -> ReLU
    {
        int base, glen, lrow;
        const float *qw, *qg, *qb;
        if (c < 21)      { base = 0;  glen = 21; lrow = c;      qw = q1w; qg = q1g; qb = q1b; }
        else if (c < 42) { base = 21; glen = 21; lrow = c - 21; qw = q2w; qg = q2g; qb = q2b; }
        else             { base = 42; glen = 22; lrow = c - 42; qw = q3w; qg = q3g; qb = q3b; }
        float sc = qg[lrow] * inv, bb = qb[lrow];
        float wr[22];
        #pragma unroll
        for (int i = 0; i < 22; i++) wr[i] = (i < glen) ? qw[lrow * glen + i] * sc : 0.0f;
        for (int t = 0; t < 16; t++) {
            int pos = pq * 16 + t;
            float acc = 0.0f;
            #pragma unroll
            for (int i = 0; i < 22; i++) acc += wr[i] * xs[(base + i) * 64 + pos];
            g_Q[((size_t)b * NPIX + n0 + pos) * CH + c] =
                __float2bfloat16(fmaxf(acc + bb, 0.0f) * QSCALE);
        }
    }

    // ---- K stage a: high = conv(x - low), lowp = conv(low)
    {
        bool hf = (c < 32);
        const float* kw = hf ? (khw + c * 64) : (klw + (c - 32) * 64);
        float kb = hf ? khb[c] : klb[c - 32];
        float wk[64];
        #pragma unroll
        for (int i = 0; i < 64; i++) wk[i] = kw[i];
        for (int t = 0; t < 16; t++) {
            int pos = pq * 16 + t;
            float acc = kb;
            if (hf) {
                #pragma unroll
                for (int i = 0; i < 64; i++) acc += wk[i] * (xs[i * 64 + pos] - ls[i * 64 + pos]);
            } else {
                #pragma unroll
                for (int i = 0; i < 64; i++) acc += wk[i] * ls[i * 64 + pos];
            }
            ts[pos * 64 + c] = acc;
        }
    }
    __syncthreads();

    // ---- K fuse
    {
        float wk[64];
        #pragma unroll
        for (int i = 0; i < 64; i++) wk[i] = kfw[c * 64 + i];
        float kb = kfb[c];
        for (int t = 0; t < 16; t++) {
            int pos = pq * 16 + t;
            float acc = kb;
            #pragma unroll
            for (int i = 0; i < 64; i++) acc += wk[i] * ts[pos * 64 + i];
            g_K[((size_t)b * NPIX + n0 + pos) * CH + c] = __float2bfloat16(acc);
        }
    }

    // ---- V: BN folded into weights
    {
        float wk[64];
        float bb = vb[c];
        #pragma unroll
        for (int i = 0; i < 64; i++) {
            float w0 = vw[c * 64 + i];
            wk[i] = w0 * (vg[i] * inv);
            bb   += w0 * vbn[i];
        }
        for (int t = 0; t < 16; t++) {
            int pos = pq * 16 + t;
            float acc = bb;
            #pragma unroll
            for (int i = 0; i < 64; i++) acc += wk[i] * xs[i * 64 + pos];
            g_V[((size_t)b * NPIX + n0 + pos) * CH + c] = __float2bfloat16(acc);
        }
    }
}

// ---------------- kernel 3: flash attention, in-block split-K x2 + fused conv ----
// 256 threads: warpgroup 0 (warps 0-3) handles keys [0,3200), warpgroup 1
// (warps 4-7) keys [3200,6400). Max-free softmax -> partials combine by simple
// addition in smem. Fused output conv + bias + residual in the epilogue.
__global__ __launch_bounds__(256) void attn_kernel(
    const float* __restrict__ x,
    const float* __restrict__ ow, const float* __restrict__ ob,
    float* __restrict__ y)
{
    extern __shared__ __align__(16) char dsm[];
    __nv_bfloat16* sQ = (__nv_bfloat16*)dsm;

    const int tid   = threadIdx.x;
    const int lane  = tid & 31;
    const int warp  = tid >> 5;
    const int wgw   = warp & 3;      // warp within warpgroup
    const int wg    = warp >> 2;     // warpgroup: key-half
    const int wtid  = tid & 127;     // thread within warpgroup
    const int b     = blockIdx.y;
    const int n0    = blockIdx.x * 64;

    const __nv_bfloat16* Qg = g_Q + ((size_t)b * NPIX + n0) * 64;
    const __nv_bfloat16* Kg = g_K + ((size_t)b * NPIX + (size_t)wg * NHALF) * 64;
    const __nv_bfloat16* Vg = g_V + ((size_t)b * NPIX + (size_t)wg * NHALF) * 64;

    const uint32_t sQ_u = (uint32_t)__cvta_generic_to_shared(sQ);
    const uint32_t wg_base = sQ_u + SQ_BYTES + wg * WG_BYTES;
    uint32_t sK_u[2], sV_u[2];
    sK_u[0] = wg_base;
    sV_u[0] = wg_base + TILE_BYTES;
    sK_u[1] = wg_base + 2 * TILE_BYTES;
    sV_u[1] = wg_base + 3 * TILE_BYTES;

    // load Q tile (64x64 bf16) into padded smem (all 256 threads)
    for (int i = tid; i < 512; i += 256) {
        int row = i >> 3, c8 = (i & 7) * 8;
        *(uint4*)(sQ + row * PIT + c8) = *(const uint4*)(Qg + row * 64 + c8);
    }

    // ldmatrix lane addressing
    const uint32_t aq_base = sQ_u + ((wgw * 16 + (lane & 15)) * PIT + (lane >> 4) * 8) * 2;
    const uint32_t bk4_off = (((lane >> 4) * 8 + (lane & 7)) * PIT) * 2 + ((lane >> 3) & 1) * 16;
    const uint32_t bk2_off = ((lane & 7) * PIT + ((lane >> 3) & 1) * 8) * 2;
    const uint32_t bv4_off = ((((lane >> 3) & 1) * 8 + (lane & 7)) * PIT + (lane >> 4) * 8) * 2;

    auto issue_tile = [&](int mt, int bb) {
        const __nv_bfloat16* Kt = Kg + (size_t)mt * 64 * 64;
        const __nv_bfloat16* Vt = Vg + (size_t)mt * 64 * 64;
        for (int i = wtid; i < 512; i += 128) {
            int row = i >> 3, c8 = (i & 7) * 8;
            CP_ASYNC16(sK_u[bb] + (row * PIT + c8) * 2, Kt + row * 64 + c8);
        }
        for (int i = wtid; i < 512; i += 128) {
            int row = i >> 3, c8 = (i & 7) * 8;
            CP_ASYNC16(sV_u[bb] + (row * PIT + c8) * 2, Vt + row * 64 + c8);
        }
        CP_COMMIT();
    };

    issue_tile(0, 0);
    __syncthreads();   // sQ visible to all

    // Q A-fragments (constant across all key tiles)
    uint32_t aq[4][4];
    #pragma unroll
    for (int kk = 0; kk < 4; kk++)
        LDSM_X4(aq[kk][0], aq[kk][1], aq[kk][2], aq[kk][3], aq_base + kk * 32);

    float l_lo = 0.0f, l_hi = 0.0f;
    float o[8][4];
    #pragma unroll
    for (int j = 0; j < 8; j++)
        #pragma unroll
        for (int q = 0; q < 4; q++) o[j][q] = 0.0f;

    for (int mt = 0; mt < NT2; mt++) {
        const int bb = mt & 1;
        if (mt + 1 < NT2) { issue_tile(mt + 1, bb ^ 1); CP_WAIT1(); }
        else              { CP_WAIT0(); }
        __syncthreads();

        // ---- S = Q . K^T
        float s[8][4];
        #pragma unroll
        for (int j = 0; j < 8; j++)
            #pragma unroll
            for (int q = 0; q < 4; q++) s[j][q] = 0.0f;

        #pragma unroll
        for (int kk = 0; kk < 4; kk++) {
            #pragma unroll
            for (int jp = 0; jp < 4; jp++) {
                uint32_t b0, b1, b2, b3;
                LDSM_X4(b0, b1, b2, b3,
                        sK_u[bb] + bk4_off + jp * (16 * PIT * 2) + kk * 32);
                MMA16816(s[2 * jp],     aq[kk][0], aq[kk][1], aq[kk][2], aq[kk][3], b0, b1);
                MMA16816(s[2 * jp + 1], aq[kk][0], aq[kk][1], aq[kk][2], aq[kk][3], b2, b3);
            }
        }

        // ---- exp2 (no max subtraction), lane-local l accumulation
        #pragma unroll
        for (int j = 0; j < 8; j++) {
            s[j][0] = exp2f(s[j][0]);
            s[j][1] = exp2f(s[j][1]);
            s[j][2] = exp2f(s[j][2]);
            s[j][3] = exp2f(s[j][3]);
            l_lo += s[j][0] + s[j][1];
            l_hi += s[j][2] + s[j][3];
        }

        // ---- O += P . V
        #pragma unroll
        for (int kb = 0; kb < 4; kb++) {
            uint32_t a0 = pack_bf16(s[2 * kb][0],     s[2 * kb][1]);
            uint32_t a1 = pack_bf16(s[2 * kb][2],     s[2 * kb][3]);
            uint32_t a2 = pack_bf16(s[2 * kb + 1][0], s[2 * kb + 1][1]);
            uint32_t a3 = pack_bf16(s[2 * kb + 1][2], s[2 * kb + 1][3]);
            #pragma unroll
            for (int jp = 0; jp < 4; jp++) {
                uint32_t b0, b1, b2, b3;
                LDSM_X4T(b0, b1, b2, b3,
                         sV_u[bb] + bv4_off + kb * (16 * PIT * 2) + jp * 32);
                MMA16816(o[2 * jp],     a0, a1, a2, a3, b0, b1);
                MMA16816(o[2 * jp + 1], a0, a1, a2, a3, b2, b3);
            }
        }
        __syncthreads();   // all reads of buf bb done before refill
    }

    // ---- l row-reduction across the quad (per warpgroup partial)
    l_lo += __shfl_xor_sync(0xffffffffu, l_lo, 1);
    l_lo += __shfl_xor_sync(0xffffffffu, l_lo, 2);
    l_hi += __shfl_xor_sync(0xffffffffu, l_hi, 1);
    l_hi += __shfl_xor_sync(0xffffffffu, l_hi, 2);

    const int r_lo = wgw * 16 + (lane >> 2);
    const int cb   = (lane & 3) * 2;

    // ---- stage ow (bf16) into sQ (dead) + wg1 dumps partials into smem
    float* cO = (float*)(dsm + SQ_BYTES);            // 64 x 65 fp32 (pad-65)
    float* cL = (float*)(dsm + SQ_BYTES + 64 * 65 * 4);  // 64 fp32
    for (int i = tid; i < 4096; i += 256) {
        int r = i >> 6, cc = i & 63;
        sQ[r * PIT + cc] = __float2bfloat16(ow[i]);
    }
    if (wg == 1) {
        #pragma unroll
        for (int j = 0; j < 8; j++) {
            cO[r_lo * 65 + 8 * j + cb]           = o[j][0];
            cO[r_lo * 65 + 8 * j + cb + 1]       = o[j][1];
            cO[(r_lo + 8) * 65 + 8 * j + cb]     = o[j][2];
            cO[(r_lo + 8) * 65 + 8 * j + cb + 1] = o[j][3];
        }
        if ((lane & 3) == 0) { cL[r_lo] = l_lo; cL[r_lo + 8] = l_hi; }
    }
    __syncthreads();

    float* sT = (float*)(dsm + SQ_BYTES + WG_BYTES);   // 64 x 65 fp32 (wg1 region)

    if (wg == 0) {
        // combine partials
        const float inv_lo = 1.0f / (l_lo + cL[r_lo]);
        const float inv_hi = 1.0f / (l_hi + cL[r_lo + 8]);
        #pragma unroll
        for (int j = 0; j < 8; j++) {
            o[j][0] += cO[r_lo * 65 + 8 * j + cb];
            o[j][1] += cO[r_lo * 65 + 8 * j + cb + 1];
            o[j][2] += cO[(r_lo + 8) * 65 + 8 * j + cb];
            o[j][3] += cO[(r_lo + 8) * 65 + 8 * j + cb + 1];
        }

        // fused conv: Y = O_norm @ W^T
        float yv[8][4];
        #pragma unroll
        for (int j = 0; j < 8; j++)
            #pragma unroll
            for (int q = 0; q < 4; q++) yv[j][q] = 0.0f;

        #pragma unroll
        for (int kk = 0; kk < 4; kk++) {
            uint32_t a0 = pack_bf16(o[2 * kk][0] * inv_lo,     o[2 * kk][1] * inv_lo);
            uint32_t a1 = pack_bf16(o[2 * kk][2] * inv_hi,     o[2 * kk][3] * inv_hi);
            uint32_t a2 = pack_bf16(o[2 * kk + 1][0] * inv_lo, o[2 * kk + 1][1] * inv_lo);
            uint32_t a3 = pack_bf16(o[2 * kk + 1][2] * inv_hi, o[2 * kk + 1][3] * inv_hi);
            #pragma unroll
            for (int j = 0; j < 8; j++) {
                uint32_t b0, b1;
                LDSM_X2(b0, b1, sQ_u + bk2_off + j * (8 * PIT * 2) + kk * 32);
                MMA16816(yv[j], a0, a1, a2, a3, b0, b1);
            }
        }

        // transpose into sT (pad-65)
        #pragma unroll
        for (int j = 0; j < 8; j++) {
            sT[r_lo * 65 + 8 * j + cb]           = yv[j][0];
            sT[r_lo * 65 + 8 * j + cb + 1]       = yv[j][1];
            sT[(r_lo + 8) * 65 + 8 * j + cb]     = yv[j][2];
            sT[(r_lo + 8) * 65 + 8 * j + cb + 1] = yv[j][3];
        }
    }
    __syncthreads();

    // ---- +bias +residual, store (all 256 threads)
    for (int i = tid; i < 4096; i += 256) {
        int cout = i >> 6, n = i & 63;
        size_t gi = (size_t)(b * CH + cout) * NPIX + n0 + n;
        y[gi] = sT[n * 65 + cout] + ob[cout] + x[gi];
    }
}

// ---------------- launch ----------------
extern "C" void kernel_launch(void* const* d_in, const int* in_sizes, int n_in,
                              void* d_out, int out_size) {
    const float* x    = (const float*)d_in[0];
    const float* q1w  = (const float*)d_in[1];
    const float* q1g  = (const float*)d_in[2];
    const float* q1b  = (const float*)d_in[3];
    const float* q2w  = (const float*)d_in[4];
    const float* q2g  = (const float*)d_in[5];
    const float* q2b  = (const float*)d_in[6];
    const float* q3w  = (const float*)d_in[7];
    const float* q3g  = (const float*)d_in[8];
    const float* q3b  = (const float*)d_in[9];
    const float* khw  = (const float*)d_in[10];
    const float* khb  = (const float*)d_in[11];
    const float* klw  = (const float*)d_in[12];
    const float* klb  = (const float*)d_in[13];
    const float* kfw  = (const float*)d_in[14];
    const float* kfb  = (const float*)d_in[15];
    const float* vg   = (const float*)d_in[16];
    const float* vbn  = (const float*)d_in[17];
    const float* vw   = (const float*)d_in[18];
    const float* vb   = (const float*)d_in[19];
    const float* ow   = (const float*)d_in[20];
    const float* ob   = (const float*)d_in[21];
    float* y = (float*)d_out;

    cudaFuncSetAttribute(attn_kernel, cudaFuncAttributeMaxDynamicSharedMemorySize, SMEM_ATTN);

    pool_kernel<<<(BATCH * CH * NPIX + 255) / 256, 256>>>(x);
    qkv_kernel<<<dim3(NPIX / 64, BATCH), 256>>>(x,
        q1w, q1g, q1b, q2w, q2g, q2b, q3w, q3g, q3b,
        khw, khb, klw, klb, kfw, kfb, vg, vbn, vw, vb);
    attn_kernel<<<dim3(NPIX / 64, BATCH), 256, SMEM_ATTN>>>(x, ow, ob, y);
}